// round 3
// baseline (speedup 1.0000x reference)
#include <cuda_runtime.h>

// Problem constants
#define B_   8
#define N_   256
#define D_   768
#define D2_  1536
#define H_   12
#define HD_  64
#define R_   10
#define EPS_ 1e-5f
// SCALE^2 / R  = (1/64)/10
#define GSCALE (1.0f / 640.0f)

// ---------------- scratch (device globals; no allocation allowed) ----------------
__device__ float g_k [R_ * N_ * D_];          // ref @ Wk        (2560 x 768)
__device__ float g_Gp[H_ * R_ * HD_ * HD_];   // per-(h,r) partial grams
__device__ float g_G [H_ * HD_ * HD_];        // Gbar_h = (s^2/R) * sum_r k^T k
__device__ float g_qv[B_ * N_ * 2 * D_];      // x @ Wqv         (2048 x 1536)
__device__ float g_M [B_ * H_ * HD_ * HD_];   // Gbar_h @ (q^T v)
__device__ float g_y [B_ * N_ * D_];          // mean_r y, flat   (2048 x 768)
__device__ float g_pr[B_ * N_ * D_];          // proj output pre-LN
__device__ float g_x [B_ * N_ * D_];          // x between steps

// =================================================================================
// 128x128x16 fp32 GEMM, 8x8 microtile, double-buffered smem, gmem reg-prefetch.
// C = A(MxK) @ B(KxN) [+bias].  Requires M%128==0, N%128==0, K%16==0.
// =================================================================================
template<bool BIAS>
__global__ __launch_bounds__(256) void sgemm128(const float* __restrict__ A,
                                                const float* __restrict__ Bm,
                                                const float* __restrict__ bias,
                                                float* __restrict__ C,
                                                int M, int N, int K)
{
    __shared__ float As[2][16][128];   // transposed A tile: As[k][m]
    __shared__ float Bs[2][16][128];   // Bs[k][n]

    const int t    = threadIdx.x;
    const int lane = t & 31;
    const int warp = t >> 5;
    // 8 warps as 4x2 grid of 32x64 warp tiles; lanes as 4x8 of 8x8 thread tiles.
    const int wrow = (warp >> 1) << 5;            // 0,32,64,96
    const int wcol = (warp & 1) << 6;             // 0,64
    const int trow = wrow + ((lane >> 3) << 3);   // 8 consecutive M rows
    const int tcol = wcol + ((lane & 7) << 3);    // 8 consecutive N cols

    const int bm = blockIdx.y << 7;
    const int bn = blockIdx.x << 7;

    // gmem load mapping (per 128x16 A tile / 16x128 B tile, 8 floats per thread)
    const int arow  = t >> 1;                     // 0..127
    const int akoff = (t & 1) << 3;               // 0 or 8
    const int bkrow = t >> 4;                     // 0..15
    const int bcol  = (t & 15) << 3;              // 0..120

    const float* Aptr = A  + (size_t)(bm + arow) * K + akoff;
    const float* Bptr = Bm + (size_t)bkrow * N + bn + bcol;

    // prologue: load k-tile 0
    float4 a0 = *(const float4*)(Aptr + 0);
    float4 a1 = *(const float4*)(Aptr + 4);
    float4 b0 = *(const float4*)(Bptr + 0);
    float4 b1 = *(const float4*)(Bptr + 4);

    As[0][akoff + 0][arow] = a0.x;
    As[0][akoff + 1][arow] = a0.y;
    As[0][akoff + 2][arow] = a0.z;
    As[0][akoff + 3][arow] = a0.w;
    As[0][akoff + 4][arow] = a1.x;
    As[0][akoff + 5][arow] = a1.y;
    As[0][akoff + 6][arow] = a1.z;
    As[0][akoff + 7][arow] = a1.w;
    *(float4*)&Bs[0][bkrow][bcol]     = b0;
    *(float4*)&Bs[0][bkrow][bcol + 4] = b1;
    __syncthreads();

    float acc[8][8] = {};
    int buf = 0;

    for (int k0 = 16; k0 <= K; k0 += 16) {
        // prefetch next tile into registers (latency hidden under compute)
        if (k0 < K) {
            a0 = *(const float4*)(Aptr + k0);
            a1 = *(const float4*)(Aptr + k0 + 4);
            b0 = *(const float4*)(Bptr + (size_t)k0 * N);
            b1 = *(const float4*)(Bptr + (size_t)k0 * N + 4);
        }

        #pragma unroll
        for (int kk = 0; kk < 16; kk++) {
            float4 fa0 = *(const float4*)&As[buf][kk][trow];
            float4 fa1 = *(const float4*)&As[buf][kk][trow + 4];
            float4 fb0 = *(const float4*)&Bs[buf][kk][tcol];
            float4 fb1 = *(const float4*)&Bs[buf][kk][tcol + 4];
            float av[8] = {fa0.x, fa0.y, fa0.z, fa0.w, fa1.x, fa1.y, fa1.z, fa1.w};
            float bv[8] = {fb0.x, fb0.y, fb0.z, fb0.w, fb1.x, fb1.y, fb1.z, fb1.w};
            #pragma unroll
            for (int i = 0; i < 8; i++)
                #pragma unroll
                for (int j = 0; j < 8; j++)
                    acc[i][j] = fmaf(av[i], bv[j], acc[i][j]);
        }

        if (k0 < K) {
            buf ^= 1;
            As[buf][akoff + 0][arow] = a0.x;
            As[buf][akoff + 1][arow] = a0.y;
            As[buf][akoff + 2][arow] = a0.z;
            As[buf][akoff + 3][arow] = a0.w;
            As[buf][akoff + 4][arow] = a1.x;
            As[buf][akoff + 5][arow] = a1.y;
            As[buf][akoff + 6][arow] = a1.z;
            As[buf][akoff + 7][arow] = a1.w;
            *(float4*)&Bs[buf][bkrow][bcol]     = b0;
            *(float4*)&Bs[buf][bkrow][bcol + 4] = b1;
            __syncthreads();
        }
    }

    // epilogue
    float4 bb0 = make_float4(0.f, 0.f, 0.f, 0.f);
    float4 bb1 = make_float4(0.f, 0.f, 0.f, 0.f);
    if (BIAS) {
        bb0 = *(const float4*)&bias[bn + tcol];
        bb1 = *(const float4*)&bias[bn + tcol + 4];
    }
    #pragma unroll
    for (int i = 0; i < 8; i++) {
        float* crow = C + (size_t)(bm + trow + i) * N + bn + tcol;
        float4 r0, r1;
        r0.x = acc[i][0] + bb0.x; r0.y = acc[i][1] + bb0.y;
        r0.z = acc[i][2] + bb0.z; r0.w = acc[i][3] + bb0.w;
        r1.x = acc[i][4] + bb1.x; r1.y = acc[i][5] + bb1.y;
        r1.z = acc[i][6] + bb1.z; r1.w = acc[i][7] + bb1.w;
        *(float4*)(crow)     = r0;
        *(float4*)(crow + 4) = r1;
    }
}

// ---------------- partial gram: for (h,r), P = k_rh^T k_rh (64x64 over 256 rows) ----
__global__ __launch_bounds__(256) void gram_partial_k()
{
    const int h = blockIdx.x, r = blockIdx.y;
    __shared__ float ks[32][64];
    const int t = threadIdx.x, ty = t >> 4, tx = t & 15;

    const float* kb = g_k + (size_t)r * N_ * D_ + h * HD_;
    float acc[4][4] = {};

    for (int c = 0; c < N_; c += 32) {
        #pragma unroll
        for (int i = 0; i < 8; i++) {
            int idx = t + i * 256;
            int nn = idx >> 6, ii = idx & 63;
            ks[nn][ii] = kb[(size_t)(c + nn) * D_ + ii];
        }
        __syncthreads();
        #pragma unroll
        for (int nn = 0; nn < 32; nn++) {
            float4 a = *(const float4*)&ks[nn][ty * 4];
            float4 b = *(const float4*)&ks[nn][tx * 4];
            float av[4] = {a.x, a.y, a.z, a.w};
            float bv[4] = {b.x, b.y, b.z, b.w};
            #pragma unroll
            for (int i = 0; i < 4; i++)
                #pragma unroll
                for (int j = 0; j < 4; j++)
                    acc[i][j] = fmaf(av[i], bv[j], acc[i][j]);
        }
        __syncthreads();
    }

    float* out = g_Gp + ((size_t)h * R_ + r) * (HD_ * HD_);
    #pragma unroll
    for (int i = 0; i < 4; i++) {
        float4 rr;
        rr.x = acc[i][0] * GSCALE; rr.y = acc[i][1] * GSCALE;
        rr.z = acc[i][2] * GSCALE; rr.w = acc[i][3] * GSCALE;
        *(float4*)&out[(ty * 4 + i) * HD_ + tx * 4] = rr;
    }
}

// ---------------- deterministic reduce over r: g_G = sum_r g_Gp ----------------
__global__ __launch_bounds__(256) void gram_reduce_k()
{
    int e = blockIdx.x * 256 + threadIdx.x;          // 0 .. H_*4096-1
    int h = e / (HD_ * HD_);
    int o = e - h * (HD_ * HD_);
    float s = 0.f;
    #pragma unroll
    for (int r = 0; r < R_; r++)
        s += g_Gp[((size_t)h * R_ + r) * (HD_ * HD_) + o];
    g_G[e] = s;
}

// ---------------- per (b,h): P = q^T v; M = Gbar_h @ P ----------------
// Smem lifetimes: {qs,vs} die before Gst is born -> union them (fits 48KB).
__global__ __launch_bounds__(256) void pm_k()
{
    const int bh = blockIdx.x;
    const int b = bh / H_, h = bh % H_;
    __shared__ union {
        struct { float qs[32][64]; float vs[32][64]; } s;
        float Gst[64][68];   // transposed Gbar, padded
    } u;
    __shared__ float Ps[64][64];
    const int t = threadIdx.x, ty = t >> 4, tx = t & 15;

    const float* qb = g_qv + (size_t)b * N_ * D2_ + h * HD_;
    const float* vb = qb + D_;

    float acc[4][4] = {};
    for (int c = 0; c < N_; c += 32) {
        #pragma unroll
        for (int i = 0; i < 8; i++) {
            int idx = t + i * 256;
            int nn = idx >> 6, ii = idx & 63;
            size_t off = (size_t)(c + nn) * D2_ + ii;
            u.s.qs[nn][ii] = qb[off];
            u.s.vs[nn][ii] = vb[off];
        }
        __syncthreads();
        #pragma unroll
        for (int nn = 0; nn < 32; nn++) {
            float4 a = *(const float4*)&u.s.qs[nn][ty * 4];
            float4 b4 = *(const float4*)&u.s.vs[nn][tx * 4];
            float av[4] = {a.x, a.y, a.z, a.w};
            float bv[4] = {b4.x, b4.y, b4.z, b4.w};
            #pragma unroll
            for (int i = 0; i < 4; i++)
                #pragma unroll
                for (int j = 0; j < 4; j++)
                    acc[i][j] = fmaf(av[i], bv[j], acc[i][j]);
        }
        __syncthreads();
    }
    // qs/vs are dead from here on (loop-closing __syncthreads passed).

    // P to smem; Gbar (transposed) into the union region
    #pragma unroll
    for (int i = 0; i < 4; i++) {
        float4 rr = make_float4(acc[i][0], acc[i][1], acc[i][2], acc[i][3]);
        *(float4*)&Ps[ty * 4 + i][tx * 4] = rr;
    }
    const float* Gb = g_G + (size_t)h * (HD_ * HD_);
    #pragma unroll
    for (int i = 0; i < 16; i++) {
        int idx = t + i * 256;
        int ig = idx >> 6, tg = idx & 63;
        u.Gst[tg][ig] = Gb[idx];
    }
    __syncthreads();

    float m4[4][4] = {};
    #pragma unroll
    for (int tt = 0; tt < 64; tt++) {
        float4 a  = *(const float4*)&u.Gst[tt][ty * 4];
        float4 b4 = *(const float4*)&Ps[tt][tx * 4];
        float av[4] = {a.x, a.y, a.z, a.w};
        float bv[4] = {b4.x, b4.y, b4.z, b4.w};
        #pragma unroll
        for (int i = 0; i < 4; i++)
            #pragma unroll
            for (int j = 0; j < 4; j++)
                m4[i][j] = fmaf(av[i], bv[j], m4[i][j]);
    }
    float* Mo = g_M + (size_t)bh * (HD_ * HD_);
    #pragma unroll
    for (int i = 0; i < 4; i++) {
        float4 rr = make_float4(m4[i][0], m4[i][1], m4[i][2], m4[i][3]);
        *(float4*)&Mo[(ty * 4 + i) * HD_ + tx * 4] = rr;
    }
}

// ---------------- per (b,h, n-chunk): y = q @ M, written flat ----------------
__global__ __launch_bounds__(256) void y_k()
{
    const int bh = blockIdx.y;
    const int b = bh / H_, h = bh % H_;
    const int n0 = blockIdx.x * 64;
    __shared__ float qt[64][68];   // transposed q tile, padded
    __shared__ float Ms[64][64];
    const int t = threadIdx.x, ty = t >> 4, tx = t & 15;

    const float* qb = g_qv + (size_t)b * N_ * D2_ + h * HD_;
    const float* Mb = g_M + (size_t)bh * (HD_ * HD_);

    #pragma unroll
    for (int i = 0; i < 16; i++) {
        int idx = t + i * 256;
        int n = idx >> 6, tt = idx & 63;
        qt[tt][n] = qb[(size_t)(n0 + n) * D2_ + tt];
        Ms[n][tt] = Mb[idx];   // n==idx>>6 is the row here too
    }
    __syncthreads();

    float acc[4][4] = {};
    #pragma unroll
    for (int tt = 0; tt < 64; tt++) {
        float4 a  = *(const float4*)&qt[tt][ty * 4];
        float4 b4 = *(const float4*)&Ms[tt][tx * 4];
        float av[4] = {a.x, a.y, a.z, a.w};
        float bv[4] = {b4.x, b4.y, b4.z, b4.w};
        #pragma unroll
        for (int i = 0; i < 4; i++)
            #pragma unroll
            for (int j = 0; j < 4; j++)
                acc[i][j] = fmaf(av[i], bv[j], acc[i][j]);
    }

    // flat layout: g_y[b][h*N*HD + n*HD + hd]  ==  rows of (2048 x 768)
    float* yo = g_y + (size_t)b * (N_ * D_) + (size_t)h * (N_ * HD_);
    #pragma unroll
    for (int i = 0; i < 4; i++) {
        int n = n0 + ty * 4 + i;
        float4 rr = make_float4(acc[i][0], acc[i][1], acc[i][2], acc[i][3]);
        *(float4*)&yo[(size_t)n * HD_ + tx * 4] = rr;
    }
}

// ---------------- layernorm over last dim (768), one block per row ----------------
__global__ __launch_bounds__(256) void ln_k(const float* __restrict__ X,
                                            const float* __restrict__ gamma,
                                            const float* __restrict__ beta,
                                            float* __restrict__ out)
{
    const int row = blockIdx.x;
    const int t = threadIdx.x;
    __shared__ float sx[768];
    __shared__ float wsum[8];
    __shared__ float wsq[8];

    const float* x = X + (size_t)row * D_;
    float s = 0.f;
    #pragma unroll
    for (int i = 0; i < 3; i++) {
        float v = x[t + i * 256];
        sx[t + i * 256] = v;
        s += v;
    }
    #pragma unroll
    for (int o = 16; o; o >>= 1) s += __shfl_xor_sync(0xffffffffu, s, o);
    if ((t & 31) == 0) wsum[t >> 5] = s;
    __syncthreads();
    float tot = 0.f;
    #pragma unroll
    for (int w = 0; w < 8; w++) tot += wsum[w];
    const float mu = tot * (1.0f / 768.0f);

    float vs = 0.f;
    #pragma unroll
    for (int i = 0; i < 3; i++) {
        float d = sx[t + i * 256] - mu;
        vs += d * d;
    }
    #pragma unroll
    for (int o = 16; o; o >>= 1) vs += __shfl_xor_sync(0xffffffffu, vs, o);
    if ((t & 31) == 0) wsq[t >> 5] = vs;
    __syncthreads();
    float tot2 = 0.f;
    #pragma unroll
    for (int w = 0; w < 8; w++) tot2 += wsq[w];
    const float rstd = rsqrtf(tot2 * (1.0f / 768.0f) + EPS_);

    #pragma unroll
    for (int i = 0; i < 3; i++) {
        int c = t + i * 256;
        out[(size_t)row * D_ + c] = (sx[c] - mu) * rstd * gamma[c] + beta[c];
    }
}

// ---------------- host orchestration ----------------
extern "C" void kernel_launch(void* const* d_in, const int* in_sizes, int n_in,
                              void* d_out, int out_size)
{
    const float* x     = (const float*)d_in[0];   // (8,256,768)
    const float* ref   = (const float*)d_in[1];   // (10,256,768)
    const float* Wqv   = (const float*)d_in[2];   // (768,1536)
    const float* Wk    = (const float*)d_in[3];   // (768,768)
    const float* Wproj = (const float*)d_in[4];   // (768,768)
    const float* bproj = (const float*)d_in[5];   // (768)
    const float* gamma = (const float*)d_in[6];   // (768)
    const float* beta  = (const float*)d_in[7];   // (768)
    float* out = (float*)d_out;

    float *pk, *pqv, *py, *ppr, *px;
    cudaGetSymbolAddress((void**)&pk,  g_k);
    cudaGetSymbolAddress((void**)&pqv, g_qv);
    cudaGetSymbolAddress((void**)&py,  g_y);
    cudaGetSymbolAddress((void**)&ppr, g_pr);
    cudaGetSymbolAddress((void**)&px,  g_x);

    // k = ref @ Wk  (2560 x 768 x 768)
    sgemm128<false><<<dim3(D_ / 128, (R_ * N_) / 128), 256>>>(ref, Wk, nullptr, pk,
                                                              R_ * N_, D_, D_);
    // Gbar_h = (s^2/R) sum_r k^T k   (deterministic two-stage)
    gram_partial_k<<<dim3(H_, R_), 256>>>();
    gram_reduce_k<<<(H_ * HD_ * HD_) / 256, 256>>>();

    for (int step = 0; step < 3; step++) {
        const float* xin = (step == 0) ? x : px;
        float* lnout = (step == 2) ? out : px;

        // qv = x @ Wqv  (2048 x 1536 x 768)
        sgemm128<false><<<dim3(D2_ / 128, (B_ * N_) / 128), 256>>>(xin, Wqv, nullptr, pqv,
                                                                   B_ * N_, D2_, D_);
        // per (b,h): M = Gbar @ (q^T v)
        pm_k<<<B_ * H_, 256>>>();
        // y = q @ M, written as (2048 x 768) flat (mean over r already folded in)
        y_k<<<dim3(N_ / 64, B_ * H_), 256>>>();
        // proj + bias
        sgemm128<true><<<dim3(D_ / 128, (B_ * N_) / 128), 256>>>(py, Wproj, bproj, ppr,
                                                                 B_ * N_, D_, D_);
        // layernorm
        ln_k<<<B_ * N_, 256>>>(ppr, gamma, beta, lnout);
    }
}

// round 5
// speedup vs baseline: 2.0819x; 2.0819x over previous
#include <cuda_runtime.h>
#include <cuda_bf16.h>
#include <cstdint>

// Problem constants
#define B_   8
#define N_   256
#define D_   768
#define D2_  1536
#define H_   12
#define HD_  64
#define R_   10
#define EPS_ 1e-5f
#define GSCALE (1.0f / 640.0f)   // SCALE^2 / R

// ---------------- scratch (device globals; no allocation allowed) ----------------
__device__ float g_k [R_ * N_ * D_];          // ref @ Wk        (2560 x 768)
__device__ float g_Gp[H_ * R_ * HD_ * HD_];   // per-(h,r) partial grams
__device__ float g_G [H_ * HD_ * HD_];        // Gbar_h
__device__ float g_qv[B_ * N_ * 2 * D_];      // x @ Wqv         (2048 x 1536)
__device__ float g_M [B_ * H_ * HD_ * HD_];   // Gbar_h @ (q^T v)
__device__ float g_y [B_ * N_ * D_];          // mean_r y, flat  (2048 x 768)
__device__ float g_pr[B_ * N_ * D_];          // proj output pre-LN
__device__ float g_x [B_ * N_ * D_];          // x between steps

// split-bf16 buffers (hi/lo). A-side sized for the largest M (2560).
__device__ __nv_bfloat16 g_ah [2560 * 768];
__device__ __nv_bfloat16 g_al [2560 * 768];
__device__ __nv_bfloat16 g_wqh[1536 * 768];   // Wqv^T hi  (N,K)
__device__ __nv_bfloat16 g_wql[1536 * 768];
__device__ __nv_bfloat16 g_wkh[ 768 * 768];   // Wk^T
__device__ __nv_bfloat16 g_wkl[ 768 * 768];
__device__ __nv_bfloat16 g_wph[ 768 * 768];   // Wproj^T
__device__ __nv_bfloat16 g_wpl[ 768 * 768];

// ================= low-level helpers (sm_80-era PTX only) =================
__device__ __forceinline__ uint32_t s2u(const void* p) {
    uint32_t a;
    asm("{ .reg .u64 t; cvta.to.shared.u64 t, %1; cvt.u32.u64 %0, t; }" : "=r"(a) : "l"(p));
    return a;
}
__device__ __forceinline__ void cp16(uint32_t sm, const void* gp) {
    asm volatile("cp.async.cg.shared.global [%0], [%1], 16;" :: "r"(sm), "l"(gp));
}
__device__ __forceinline__ void cp_commit() { asm volatile("cp.async.commit_group;"); }
__device__ __forceinline__ void cp_wait0()  { asm volatile("cp.async.wait_group 0;"); }
__device__ __forceinline__ void cp_wait1()  { asm volatile("cp.async.wait_group 1;"); }

__device__ __forceinline__ void ldsm4(uint32_t* r, uint32_t a) {
    asm volatile("ldmatrix.sync.aligned.m8n8.x4.shared.b16 {%0,%1,%2,%3}, [%4];"
                 : "=r"(r[0]), "=r"(r[1]), "=r"(r[2]), "=r"(r[3]) : "r"(a));
}
__device__ __forceinline__ void mma16816(float* c, const uint32_t* a, const uint32_t* b) {
    asm volatile("mma.sync.aligned.m16n8k16.row.col.f32.bf16.bf16.f32 "
                 "{%0,%1,%2,%3}, {%4,%5,%6,%7}, {%8,%9}, {%0,%1,%2,%3};"
                 : "+f"(c[0]), "+f"(c[1]), "+f"(c[2]), "+f"(c[3])
                 : "r"(a[0]), "r"(a[1]), "r"(a[2]), "r"(a[3]), "r"(b[0]), "r"(b[1]));
}

// ================= split kernels =================
__global__ __launch_bounds__(256) void split_k(const float* __restrict__ X,
                                               __nv_bfloat16* __restrict__ hi,
                                               __nv_bfloat16* __restrict__ lo)
{
    size_t i = ((size_t)blockIdx.x * 256 + threadIdx.x) * 8;
    float4 a = *(const float4*)(X + i);
    float4 b = *(const float4*)(X + i + 4);
    float v[8] = {a.x, a.y, a.z, a.w, b.x, b.y, b.z, b.w};
    __nv_bfloat16 h[8], l[8];
    #pragma unroll
    for (int j = 0; j < 8; j++) {
        h[j] = __float2bfloat16(v[j]);
        l[j] = __float2bfloat16(v[j] - __bfloat162float(h[j]));
    }
    *(uint4*)(hi + i) = *(const uint4*)h;
    *(uint4*)(lo + i) = *(const uint4*)l;
}

// W (K,N) fp32 -> W^T (N,K) hi/lo bf16, tiled transpose.
__global__ __launch_bounds__(256) void splitT_k(const float* __restrict__ W,
                                                __nv_bfloat16* __restrict__ hiT,
                                                __nv_bfloat16* __restrict__ loT,
                                                int K, int N)
{
    __shared__ float sm[32][33];
    const int n0 = blockIdx.x * 32, k0 = blockIdx.y * 32;
    const int tx = threadIdx.x & 31, ty = threadIdx.x >> 5;   // 32 x 8
    #pragma unroll
    for (int i = 0; i < 4; i++)
        sm[ty + i * 8][tx] = W[(size_t)(k0 + ty + i * 8) * N + n0 + tx];
    __syncthreads();
    #pragma unroll
    for (int i = 0; i < 4; i++) {
        int n = n0 + ty + i * 8;
        float v = sm[tx][ty + i * 8];
        __nv_bfloat16 h = __float2bfloat16(v);
        hiT[(size_t)n * K + k0 + tx] = h;
        loT[(size_t)n * K + k0 + tx] = __float2bfloat16(v - __bfloat162float(h));
    }
}

// ================= HMMA split-bf16 GEMM =================
// C(M,N) = (ah+al)(M,K) @ (bh+bl)^T  with bt stored (N,K) K-contiguous.
// CTA tile 128x64, 8 warps (4x2 of 32x32 warp tiles), k-block 32, double buffer.
// smem rows padded to 80B (odd*16 mod 128 -> ldmatrix conflict-free).
// Per buffer: Ah@0(10240) Al@10240 Bh@20480(5120) Bl@25600; buf stride 30720.
#define HG_BUF   30720
#define HG_TOTAL (2 * HG_BUF)

template<bool BIAS>
__global__ __launch_bounds__(256) void hgemm(const __nv_bfloat16* __restrict__ ah,
                                             const __nv_bfloat16* __restrict__ al,
                                             const __nv_bfloat16* __restrict__ bh,
                                             const __nv_bfloat16* __restrict__ bl,
                                             const float* __restrict__ bias,
                                             float* __restrict__ C,
                                             int M, int N, int K)
{
    extern __shared__ char smraw[];
    const uint32_t sb = s2u(smraw);
    const int t = threadIdx.x, warp = t >> 5, lane = t & 31;
    const int wm = warp >> 1, wn = warp & 1;          // 4 x 2 warp grid
    const int bm = blockIdx.y << 7, bn = blockIdx.x << 6;

    // cp.async source/dest precompute: 6 chunks of 16B per thread per k-block
    // c < 1024 -> A tiles (hi/lo), else B tiles.
    uint32_t s_dst[6];
    const __nv_bfloat16* s_srcb[6];
    #pragma unroll
    for (int i = 0; i < 6; i++) {
        int c = t + (i << 8);
        if (c < 1024) {
            int hi = (c < 512);
            int cc = c & 511, row = cc >> 2, ch = cc & 3;
            s_srcb[i] = (hi ? ah : al) + (size_t)(bm + row) * K + (ch << 3);
            s_dst[i]  = (hi ? 0u : 10240u) + row * 80 + (ch << 4);
        } else {
            int d = c - 1024;
            int hi = (d < 256);
            int cc = d & 255, row = cc >> 2, ch = cc & 3;
            s_srcb[i] = (hi ? bh : bl) + (size_t)(bn + row) * K + (ch << 3);
            s_dst[i]  = 20480u + (hi ? 0u : 5120u) + row * 80 + (ch << 4);
        }
    }

    // ldmatrix per-lane offsets
    const int g = lane >> 3, r = lane & 7;
    const uint32_t a_off = (uint32_t)((((g & 1) << 3) + r) * 80 + ((g >> 1) << 4));
    const uint32_t b_off = (uint32_t)((((g >> 1) << 3) + r) * 80 + ((g & 1) << 4));
    const uint32_t aw = (uint32_t)(wm * 32) * 80;       // warp m base within tile
    const uint32_t bw = (uint32_t)(wn * 32) * 80;       // warp n base within tile

    float acc[2][4][4] = {};

    const int nb = K >> 5;
    // prologue: block 0 -> buf 0
    #pragma unroll
    for (int i = 0; i < 6; i++) cp16(sb + s_dst[i], s_srcb[i]);
    cp_commit();

    uint32_t bufo = 0;
    for (int blk = 0; blk < nb; blk++) {
        if (blk + 1 < nb) {
            const int k0 = (blk + 1) << 5;
            const uint32_t nxt = bufo ^ HG_BUF;
            #pragma unroll
            for (int i = 0; i < 6; i++) cp16(sb + nxt + s_dst[i], s_srcb[i] + k0);
            cp_commit();
            cp_wait1();
        } else {
            cp_wait0();
        }
        __syncthreads();

        const uint32_t sA = sb + bufo;
        const uint32_t sB = sb + bufo + 20480u;
        #pragma unroll
        for (int ks = 0; ks < 2; ks++) {
            const uint32_t kso = (uint32_t)(ks << 5);
            uint32_t fah[2][4], fal[2][4], fbh[8], fbl[8];
            #pragma unroll
            for (int ms = 0; ms < 2; ms++) {
                ldsm4(fah[ms], sA +          aw + (uint32_t)(ms * 16) * 80 + kso + a_off);
                ldsm4(fal[ms], sA + 10240u + aw + (uint32_t)(ms * 16) * 80 + kso + a_off);
            }
            #pragma unroll
            for (int ns = 0; ns < 2; ns++) {
                ldsm4(fbh + ns * 4, sB +         bw + (uint32_t)(ns * 16) * 80 + kso + b_off);
                ldsm4(fbl + ns * 4, sB + 5120u + bw + (uint32_t)(ns * 16) * 80 + kso + b_off);
            }
            #pragma unroll
            for (int ms = 0; ms < 2; ms++)
                #pragma unroll
                for (int ng = 0; ng < 4; ng++) {
                    mma16816(acc[ms][ng], fah[ms], fbh + ng * 2);
                    mma16816(acc[ms][ng], fah[ms], fbl + ng * 2);
                    mma16816(acc[ms][ng], fal[ms], fbh + ng * 2);
                }
        }
        __syncthreads();
        bufo ^= HG_BUF;
    }

    // epilogue: lane l owns (row = base+l/4 [,+8], col = base+ (l%4)*2, +1)
    const int mb = bm + wm * 32;
    const int nbase = bn + wn * 32;
    #pragma unroll
    for (int ms = 0; ms < 2; ms++) {
        const int m0 = mb + ms * 16 + (lane >> 2);
        #pragma unroll
        for (int ng = 0; ng < 4; ng++) {
            const int col = nbase + ng * 8 + ((lane & 3) << 1);
            float bx = 0.f, by = 0.f;
            if (BIAS) { bx = bias[col]; by = bias[col + 1]; }
            float2 v0 = make_float2(acc[ms][ng][0] + bx, acc[ms][ng][1] + by);
            float2 v1 = make_float2(acc[ms][ng][2] + bx, acc[ms][ng][3] + by);
            *(float2*)(C + (size_t)m0 * N + col)       = v0;
            *(float2*)(C + (size_t)(m0 + 8) * N + col) = v1;
        }
    }
}

// ---------------- partial gram: for (h,r), P = k_rh^T k_rh ----------------
__global__ __launch_bounds__(256) void gram_partial_k()
{
    const int h = blockIdx.x, r = blockIdx.y;
    __shared__ float ks[32][64];
    const int t = threadIdx.x, ty = t >> 4, tx = t & 15;
    const float* kb = g_k + (size_t)r * N_ * D_ + h * HD_;
    float acc[4][4] = {};
    for (int c = 0; c < N_; c += 32) {
        #pragma unroll
        for (int i = 0; i < 8; i++) {
            int idx = t + i * 256;
            int nn = idx >> 6, ii = idx & 63;
            ks[nn][ii] = kb[(size_t)(c + nn) * D_ + ii];
        }
        __syncthreads();
        #pragma unroll
        for (int nn = 0; nn < 32; nn++) {
            float4 a = *(const float4*)&ks[nn][ty * 4];
            float4 b = *(const float4*)&ks[nn][tx * 4];
            float av[4] = {a.x, a.y, a.z, a.w};
            float bv[4] = {b.x, b.y, b.z, b.w};
            #pragma unroll
            for (int i = 0; i < 4; i++)
                #pragma unroll
                for (int j = 0; j < 4; j++)
                    acc[i][j] = fmaf(av[i], bv[j], acc[i][j]);
        }
        __syncthreads();
    }
    float* out = g_Gp + ((size_t)h * R_ + r) * (HD_ * HD_);
    #pragma unroll
    for (int i = 0; i < 4; i++) {
        float4 rr;
        rr.x = acc[i][0] * GSCALE; rr.y = acc[i][1] * GSCALE;
        rr.z = acc[i][2] * GSCALE; rr.w = acc[i][3] * GSCALE;
        *(float4*)&out[(ty * 4 + i) * HD_ + tx * 4] = rr;
    }
}

__global__ __launch_bounds__(256) void gram_reduce_k()
{
    int e = blockIdx.x * 256 + threadIdx.x;
    int h = e / (HD_ * HD_);
    int o = e - h * (HD_ * HD_);
    float s = 0.f;
    #pragma unroll
    for (int r = 0; r < R_; r++)
        s += g_Gp[((size_t)h * R_ + r) * (HD_ * HD_) + o];
    g_G[e] = s;
}

// ---------------- per (b,h): P = q^T v; M = Gbar_h @ P ----------------
__global__ __launch_bounds__(256) void pm_k()
{
    const int bh = blockIdx.x;
    const int b = bh / H_, h = bh % H_;
    __shared__ union {
        struct { float qs[32][64]; float vs[32][64]; } s;
        float Gst[64][68];
    } u;
    __shared__ float Ps[64][64];
    const int t = threadIdx.x, ty = t >> 4, tx = t & 15;
    const float* qb = g_qv + (size_t)b * N_ * D2_ + h * HD_;
    const float* vb = qb + D_;

    float acc[4][4] = {};
    for (int c = 0; c < N_; c += 32) {
        #pragma unroll
        for (int i = 0; i < 8; i++) {
            int idx = t + i * 256;
            int nn = idx >> 6, ii = idx & 63;
            size_t off = (size_t)(c + nn) * D2_ + ii;
            u.s.qs[nn][ii] = qb[off];
            u.s.vs[nn][ii] = vb[off];
        }
        __syncthreads();
        #pragma unroll
        for (int nn = 0; nn < 32; nn++) {
            float4 a = *(const float4*)&u.s.qs[nn][ty * 4];
            float4 b4 = *(const float4*)&u.s.vs[nn][tx * 4];
            float av[4] = {a.x, a.y, a.z, a.w};
            float bv[4] = {b4.x, b4.y, b4.z, b4.w};
            #pragma unroll
            for (int i = 0; i < 4; i++)
                #pragma unroll
                for (int j = 0; j < 4; j++)
                    acc[i][j] = fmaf(av[i], bv[j], acc[i][j]);
        }
        __syncthreads();
    }
    #pragma unroll
    for (int i = 0; i < 4; i++) {
        float4 rr = make_float4(acc[i][0], acc[i][1], acc[i][2], acc[i][3]);
        *(float4*)&Ps[ty * 4 + i][tx * 4] = rr;
    }
    const float* Gb = g_G + (size_t)h * (HD_ * HD_);
    #pragma unroll
    for (int i = 0; i < 16; i++) {
        int idx = t + i * 256;
        int ig = idx >> 6, tg = idx & 63;
        u.Gst[tg][ig] = Gb[idx];
    }
    __syncthreads();

    float m4[4][4] = {};
    #pragma unroll
    for (int tt = 0; tt < 64; tt++) {
        float4 a  = *(const float4*)&u.Gst[tt][ty * 4];
        float4 b4 = *(const float4*)&Ps[tt][tx * 4];
        float av[4] = {a.x, a.y, a.z, a.w};
        float bv[4] = {b4.x, b4.y, b4.z, b4.w};
        #pragma unroll
        for (int i = 0; i < 4; i++)
            #pragma unroll
            for (int j = 0; j < 4; j++)
                m4[i][j] = fmaf(av[i], bv[j], m4[i][j]);
    }
    float* Mo = g_M + (size_t)bh * (HD_ * HD_);
    #pragma unroll
    for (int i = 0; i < 4; i++) {
        float4 rr = make_float4(m4[i][0], m4[i][1], m4[i][2], m4[i][3]);
        *(float4*)&Mo[(ty * 4 + i) * HD_ + tx * 4] = rr;
    }
}

// ---------------- per (b,h, n-chunk): y = q @ M, written flat ----------------
__global__ __launch_bounds__(256) void y_k()
{
    const int bh = blockIdx.y;
    const int b = bh / H_, h = bh % H_;
    const int n0 = blockIdx.x * 64;
    __shared__ float qt[64][68];
    __shared__ float Ms[64][64];
    const int t = threadIdx.x, ty = t >> 4, tx = t & 15;
    const float* qb = g_qv + (size_t)b * N_ * D2_ + h * HD_;
    const float* Mb = g_M + (size_t)bh * (HD_ * HD_);

    #pragma unroll
    for (int i = 0; i < 16; i++) {
        int idx = t + i * 256;
        int n = idx >> 6, tt = idx & 63;
        qt[tt][n] = qb[(size_t)(n0 + n) * D2_ + tt];
        Ms[n][tt] = Mb[idx];
    }
    __syncthreads();

    float acc[4][4] = {};
    #pragma unroll
    for (int tt = 0; tt < 64; tt++) {
        float4 a  = *(const float4*)&qt[tt][ty * 4];
        float4 b4 = *(const float4*)&Ms[tt][tx * 4];
        float av[4] = {a.x, a.y, a.z, a.w};
        float bv[4] = {b4.x, b4.y, b4.z, b4.w};
        #pragma unroll
        for (int i = 0; i < 4; i++)
            #pragma unroll
            for (int j = 0; j < 4; j++)
                acc[i][j] = fmaf(av[i], bv[j], acc[i][j]);
    }
    float* yo = g_y + (size_t)b * (N_ * D_) + (size_t)h * (N_ * HD_);
    #pragma unroll
    for (int i = 0; i < 4; i++) {
        int n = n0 + ty * 4 + i;
        float4 rr = make_float4(acc[i][0], acc[i][1], acc[i][2], acc[i][3]);
        *(float4*)&yo[(size_t)n * HD_ + tx * 4] = rr;
    }
}

// ---------------- layernorm ----------------
__global__ __launch_bounds__(256) void ln_k(const float* __restrict__ X,
                                            const float* __restrict__ gamma,
                                            const float* __restrict__ beta,
                                            float* __restrict__ out)
{
    const int row = blockIdx.x;
    const int t = threadIdx.x;
    __shared__ float sx[768];
    __shared__ float wsum[8];
    __shared__ float wsq[8];
    const float* x = X + (size_t)row * D_;
    float s = 0.f;
    #pragma unroll
    for (int i = 0; i < 3; i++) {
        float v = x[t + i * 256];
        sx[t + i * 256] = v;
        s += v;
    }
    #pragma unroll
    for (int o = 16; o; o >>= 1) s += __shfl_xor_sync(0xffffffffu, s, o);
    if ((t & 31) == 0) wsum[t >> 5] = s;
    __syncthreads();
    float tot = 0.f;
    #pragma unroll
    for (int w = 0; w < 8; w++) tot += wsum[w];
    const float mu = tot * (1.0f / 768.0f);
    float vs = 0.f;
    #pragma unroll
    for (int i = 0; i < 3; i++) {
        float d = sx[t + i * 256] - mu;
        vs += d * d;
    }
    #pragma unroll
    for (int o = 16; o; o >>= 1) vs += __shfl_xor_sync(0xffffffffu, vs, o);
    if ((t & 31) == 0) wsq[t >> 5] = vs;
    __syncthreads();
    float tot2 = 0.f;
    #pragma unroll
    for (int w = 0; w < 8; w++) tot2 += wsq[w];
    const float rstd = rsqrtf(tot2 * (1.0f / 768.0f) + EPS_);
    #pragma unroll
    for (int i = 0; i < 3; i++) {
        int c = t + i * 256;
        out[(size_t)row * D_ + c] = (sx[c] - mu) * rstd * gamma[c] + beta[c];
    }
}

// ---------------- host orchestration ----------------
extern "C" void kernel_launch(void* const* d_in, const int* in_sizes, int n_in,
                              void* d_out, int out_size)
{
    const float* x     = (const float*)d_in[0];   // (8,256,768)
    const float* ref   = (const float*)d_in[1];   // (10,256,768)
    const float* Wqv   = (const float*)d_in[2];   // (768,1536)
    const float* Wk    = (const float*)d_in[3];   // (768,768)
    const float* Wproj = (const float*)d_in[4];   // (768,768)
    const float* bproj = (const float*)d_in[5];   // (768)
    const float* gamma = (const float*)d_in[6];   // (768)
    const float* beta  = (const float*)d_in[7];   // (768)
    float* out = (float*)d_out;

    cudaFuncSetAttribute(hgemm<false>, cudaFuncAttributeMaxDynamicSharedMemorySize, HG_TOTAL);
    cudaFuncSetAttribute(hgemm<true>,  cudaFuncAttributeMaxDynamicSharedMemorySize, HG_TOTAL);

    float *pk, *pqv, *py, *ppr, *px;
    cudaGetSymbolAddress((void**)&pk,  g_k);
    cudaGetSymbolAddress((void**)&pqv, g_qv);
    cudaGetSymbolAddress((void**)&py,  g_y);
    cudaGetSymbolAddress((void**)&ppr, g_pr);
    cudaGetSymbolAddress((void**)&px,  g_x);
    __nv_bfloat16 *pah, *pal, *pwqh, *pwql, *pwkh, *pwkl, *pwph, *pwpl;
    cudaGetSymbolAddress((void**)&pah,  g_ah);
    cudaGetSymbolAddress((void**)&pal,  g_al);
    cudaGetSymbolAddress((void**)&pwqh, g_wqh);
    cudaGetSymbolAddress((void**)&pwql, g_wql);
    cudaGetSymbolAddress((void**)&pwkh, g_wkh);
    cudaGetSymbolAddress((void**)&pwkl, g_wkl);
    cudaGetSymbolAddress((void**)&pwph, g_wph);
    cudaGetSymbolAddress((void**)&pwpl, g_wpl);

    // weight splits (+transpose to (N,K)) — once per launch
    splitT_k<<<dim3(D2_ / 32, D_ / 32), 256>>>(Wqv,   pwqh, pwql, D_, D2_);
    splitT_k<<<dim3(D_  / 32, D_ / 32), 256>>>(Wk,    pwkh, pwkl, D_, D_);
    splitT_k<<<dim3(D_  / 32, D_ / 32), 256>>>(Wproj, pwph, pwpl, D_, D_);

    // k = ref @ Wk  (2560 x 768 x 768)
    split_k<<<(R_ * N_ * D_) / 2048, 256>>>(ref, pah, pal);
    hgemm<false><<<dim3(D_ / 64, (R_ * N_) / 128), 256, HG_TOTAL>>>(
        pah, pal, pwkh, pwkl, nullptr, pk, R_ * N_, D_, D_);

    gram_partial_k<<<dim3(H_, R_), 256>>>();
    gram_reduce_k<<<(H_ * HD_ * HD_) / 256, 256>>>();

    for (int step = 0; step < 3; step++) {
        const float* xin = (step == 0) ? x : px;
        float* lnout = (step == 2) ? out : px;

        split_k<<<(B_ * N_ * D_) / 2048, 256>>>(xin, pah, pal);
        hgemm<false><<<dim3(D2_ / 64, (B_ * N_) / 128), 256, HG_TOTAL>>>(
            pah, pal, pwqh, pwql, nullptr, pqv, B_ * N_, D2_, D_);

        pm_k<<<B_ * H_, 256>>>();
        y_k<<<dim3(N_ / 64, B_ * H_), 256>>>();

        split_k<<<(B_ * N_ * D_) / 2048, 256>>>(py, pah, pal);
        hgemm<true><<<dim3(D_ / 64, (B_ * N_) / 128), 256, HG_TOTAL>>>(
            pah, pal, pwph, pwpl, bproj, ppr, B_ * N_, D_, D_);

        ln_k<<<B_ * N_, 256>>>(ppr, gamma, beta, lnout);
    }
}